// round 11
// baseline (speedup 1.0000x reference)
#include <cuda_runtime.h>
#include <math.h>
#include <limits.h>

// WARP loss, R11: R10 + fully-hoisted candidate gathers.
// The gather loads (neg line -> 16 input gathers) do NOT depend on the
// positive score -- only the accept comparison does. Issue them at kernel
// entry so the 2-deep gather chain overlaps probe 1 entirely; the post-scan
// tail is then pure ALU. Scan: two probes 20KB/20KB (E[rounds]=1.49).
// Traffic: scan ~122MB + gathers ~8MB + neg 2MB ~= 132MB.

#define NT 256
#define P_VEC 5          // 5 float4/thread per probe = 20KB (NT=256)
#define BATCH1 16        // trials gathered eagerly (P[all reject] ~ 0.3%)

__global__ __launch_bounds__(NT, 8)
void warp_loss_kernel(const float* __restrict__ input,
                      const float* __restrict__ target,
                      const int*   __restrict__ neg,
                      float* __restrict__ out,
                      int Y, int T) {
    const int row  = blockIdx.x;
    const int tid  = threadIdx.x;
    const int lane = tid & 31;
    const int wid  = tid >> 5;
    const float* irow = input  + (size_t)row * Y;
    const float* trow = target + (size_t)row * Y;

    __shared__ float sc_sh[128];      // candidate scores (fallback path)
    __shared__ float s_pscore;        // positive score
    __shared__ int   s_first1;        // first accepted among trials 0..BATCH1-1
    __shared__ int   s_first_w[4];    // per-warp mins (fallback)

    // --- Phase 0: eager candidate gathers (independent of sp) ---
    // warp 0: one 64B neg read + 16 scattered input reads; chain starts at
    // entry and overlaps the whole scan below.
    float sc_pre = 0.0f;
    if (wid == 0) {
        int c = 0;
        if (lane < BATCH1) c = __ldg(&neg[(size_t)row * T + lane]);
        sc_pre = __ldg(&irow[c]);      // lanes >= BATCH1 read irow[0] (bcast)
    }

    const int nvec = Y >> 2;                        // 2500 for Y=10000
    const float4* tv = reinterpret_cast<const float4*>(trow);
    const float4 zero4 = make_float4(0.f, 0.f, 0.f, 0.f);

    // --- Probe 1: first 20KB, all loads in flight before any test ---
    {
        float4 v[P_VEC]; int idx[P_VEC];
#pragma unroll
        for (int k = 0; k < P_VEC; k++) {
            idx[k] = k * NT + tid;
            v[k] = (idx[k] < nvec) ? __ldg(&tv[idx[k]]) : zero4;
        }
        int p = -1;
#pragma unroll
        for (int k = 0; k < P_VEC; k++) {
            if (v[k].x != 0.0f) p = 4 * idx[k];
            if (v[k].y != 0.0f) p = 4 * idx[k] + 1;
            if (v[k].z != 0.0f) p = 4 * idx[k] + 2;
            if (v[k].w != 0.0f) p = 4 * idx[k] + 3;
        }
        if (p >= 0) s_pscore = __ldg(&irow[p]);
        if (!__syncthreads_or(p >= 0)) {
            // --- Probe 2: remaining ~19.5KB ---
            float4 w[P_VEC]; int jdx[P_VEC];
#pragma unroll
            for (int k = 0; k < P_VEC; k++) {
                jdx[k] = (P_VEC + k) * NT + tid;
                w[k] = (jdx[k] < nvec) ? __ldg(&tv[jdx[k]]) : zero4;
            }
            int q = -1;
#pragma unroll
            for (int k = 0; k < P_VEC; k++) {
                if (w[k].x != 0.0f) q = 4 * jdx[k];
                if (w[k].y != 0.0f) q = 4 * jdx[k] + 1;
                if (w[k].z != 0.0f) q = 4 * jdx[k] + 2;
                if (w[k].w != 0.0f) q = 4 * jdx[k] + 3;
            }
            for (int i = (nvec << 2) + tid; i < Y; i += NT)   // scalar tail
                if (trow[i] != 0.0f) q = i;
            if (q >= 0) s_pscore = __ldg(&irow[q]);
            __syncthreads();
        }
    }
    const float sp = s_pscore;

    // --- Batch 1: trials 0..15 (scores already in registers; pure ALU) ---
    if (wid == 0) {
        const bool acc = (lane < BATCH1) && (1.0f + sc_pre - sp >= 0.0f);
        const unsigned m = __ballot_sync(0xFFFFFFFFu, acc);
        const int first = m ? (__ffs(m) - 1) : INT_MAX;
        if (first != INT_MAX) {
            const float sn = __shfl_sync(0xFFFFFFFFu, sc_pre, first);
            if (lane == 0) {
                s_first1 = first;
                const int num_trials = first + 1;
                const float L = logf((float)((Y - 1) / num_trials));
                atomicAdd(out, L * (1.0f - sp + sn));
            }
        } else if (lane == 0) {
            s_first1 = INT_MAX;
        }
    }
    __syncthreads();

    // --- Fallback (rare, ~0.3%): trials BATCH1..T-1 on threads BATCH1..T-1 ---
    if (s_first1 == INT_MAX && T > BATCH1) {
        bool acc = false;
        if (tid >= BATCH1 && tid < T) {
            const int c = __ldg(&neg[(size_t)row * T + tid]);
            const float sc = __ldg(&irow[c]);
            sc_sh[tid] = sc;
            acc = (1.0f + sc - sp >= 0.0f);
        }
        const unsigned m = __ballot_sync(0xFFFFFFFFu, acc);
        if (lane == 0) s_first_w[wid] = m ? (wid * 32 + __ffs(m) - 1) : INT_MAX;
        __syncthreads();
        if (tid == 0) {
            int first = s_first_w[0];
            first = min(first, s_first_w[1]);
            first = min(first, s_first_w[2]);
            first = min(first, s_first_w[3]);
            if (first != INT_MAX) {
                const int num_trials = first + 1;
                const float L = logf((float)((Y - 1) / num_trials));
                atomicAdd(out, L * (1.0f - sp + sc_sh[first]));
            }
        }
    }
}

extern "C" void kernel_launch(void* const* d_in, const int* in_sizes, int n_in,
                              void* d_out, int out_size) {
    const float* input  = (const float*)d_in[0];
    const float* target = (const float*)d_in[1];
    const int*   neg    = (const int*)d_in[2];
    float* out = (float*)d_out;

    const int Y = 10000;                 // fixed by problem spec
    const int B = in_sizes[0] / Y;       // 4096
    const int T = in_sizes[2] / B;       // 128

    cudaMemsetAsync(out, 0, (size_t)out_size * sizeof(float), 0);
    warp_loss_kernel<<<B, NT>>>(input, target, neg, out, Y, T);
}

// round 12
// speedup vs baseline: 1.4137x; 1.4137x over previous
#include <cuda_runtime.h>
#include <math.h>
#include <limits.h>

// WARP loss, R12: warp-per-row with double-buffered 2KB chunk scan.
// Fine-grained early exit (2KB) WITHOUT serialized latency: chunk c+1 is
// always in flight while chunk c is tested, so a row's scan proceeds at its
// bandwidth share instead of chunk-count x DRAM-latency (R5's failure).
// Lazy 16-candidate gather (fallback ~0.3%) hoisted to entry.
// Ledger: scan ~96MB + gathers ~8MB + neg ~2MB ~= 113MB. No __syncthreads.

#define FULL 0xFFFFFFFFu
#define BATCH1 16
#define CV 4                       // float4 per lane per chunk (2KB/warp-chunk)
#define CHUNK (CV * 32)            // float4 per chunk = 128 -> 2KB

__global__ __launch_bounds__(256, 4)
void warp_loss_kernel(const float* __restrict__ input,
                      const float* __restrict__ target,
                      const int*   __restrict__ neg,
                      float* __restrict__ out,
                      int B, int T) {
    constexpr int Y    = 10000;
    constexpr int nvec = Y >> 2;                       // 2500 float4
    constexpr int NCH  = (nvec + CHUNK - 1) / CHUNK;   // 20 chunks

    const int gw   = blockIdx.x * 8 + (threadIdx.x >> 5);
    const int lane = threadIdx.x & 31;
    if (gw >= B) return;                               // warp-uniform

    const float* irow = input  + (size_t)gw * Y;
    const float* trow = target + (size_t)gw * Y;
    const float4* tv  = reinterpret_cast<const float4*>(trow);
    const float4 zero4 = make_float4(0.f, 0.f, 0.f, 0.f);

    // --- eager gather of first BATCH1 trials (independent of sp) ---
    int c_pre = 0;
    if (lane < BATCH1) c_pre = __ldg(&neg[(size_t)gw * T + lane]);
    const float sc_pre = __ldg(&irow[c_pre]);          // lanes>=16: bcast irow[0]

#define LOADC(buf, ch)                                              \
    {                                                               \
        _Pragma("unroll")                                           \
        for (int k = 0; k < CV; k++) {                              \
            const int _i = (ch) * CHUNK + k * 32 + lane;            \
            buf[k] = (_i < nvec) ? __ldg(&tv[_i]) : zero4;          \
        }                                                           \
    }
#define TESTC(buf, ch, pvar)                                        \
    {                                                               \
        _Pragma("unroll")                                           \
        for (int k = 0; k < CV; k++) {                              \
            const int _i = (ch) * CHUNK + k * 32 + lane;            \
            if (buf[k].x != 0.0f) pvar = 4 * _i;                    \
            if (buf[k].y != 0.0f) pvar = 4 * _i + 1;                \
            if (buf[k].z != 0.0f) pvar = 4 * _i + 2;                \
            if (buf[k].w != 0.0f) pvar = 4 * _i + 3;                \
        }                                                           \
    }

    // --- double-buffered scan: prefetch ch+1 while testing ch ---
    int pos = -1;
    {
        float4 A[CV], Bb[CV];
        LOADC(A, 0);
#pragma unroll
        for (int ch = 0; ch < NCH; ch += 2) {
            if (ch + 1 < NCH) LOADC(Bb, ch + 1);
            int p = -1;
            TESTC(A, ch, p);
            if (__ballot_sync(FULL, p >= 0)) {
                pos = __reduce_min_sync(FULL, p >= 0 ? p : INT_MAX);
                break;
            }
            if (ch + 2 < NCH) LOADC(A, ch + 2);
            p = -1;
            if (ch + 1 < NCH) TESTC(Bb, ch + 1, p);
            if (__ballot_sync(FULL, p >= 0)) {
                pos = __reduce_min_sync(FULL, p >= 0 ? p : INT_MAX);
                break;
            }
        }
    }
    if (pos < 0) pos = 0;                              // defensive (one-hot row)

    const float sp = __ldg(&irow[pos]);                // broadcast load

    // --- first accepted among trials 0..15 (scores already in regs) ---
    const bool acc = (lane < BATCH1) && (1.0f + sc_pre - sp >= 0.0f);
    const unsigned m = __ballot_sync(FULL, acc);
    if (m) {
        const int first = __ffs(m) - 1;
        const float sn = __shfl_sync(FULL, sc_pre, first);
        if (lane == 0) {
            const int num_trials = first + 1;
            const float L = logf((float)((Y - 1) / num_trials));
            atomicAdd(out, L * (1.0f - sp + sn));
        }
    } else {
        // --- fallback (rare): trials BATCH1..T-1, 32 at a time ---
        for (int t0 = BATCH1; t0 < T; t0 += 32) {
            const int t = t0 + lane;
            int c = 0;
            if (t < T) c = __ldg(&neg[(size_t)gw * T + t]);
            const float sc = __ldg(&irow[c]);
            const bool a2 = (t < T) && (1.0f + sc - sp >= 0.0f);
            const unsigned m2 = __ballot_sync(FULL, a2);
            if (m2) {
                const int fl = __ffs(m2) - 1;
                const float sn = __shfl_sync(FULL, sc, fl);
                if (lane == 0) {
                    const int num_trials = t0 + fl + 1;
                    const float L = logf((float)((Y - 1) / num_trials));
                    atomicAdd(out, L * (1.0f - sp + sn));
                }
                break;
            }
        }
    }
#undef LOADC
#undef TESTC
}

extern "C" void kernel_launch(void* const* d_in, const int* in_sizes, int n_in,
                              void* d_out, int out_size) {
    const float* input  = (const float*)d_in[0];
    const float* target = (const float*)d_in[1];
    const int*   neg    = (const int*)d_in[2];
    float* out = (float*)d_out;

    const int Y = 10000;                 // fixed by problem spec
    const int B = in_sizes[0] / Y;       // 4096
    const int T = in_sizes[2] / B;       // 128

    cudaMemsetAsync(out, 0, (size_t)out_size * sizeof(float), 0);
    warp_loss_kernel<<<(B + 7) / 8, 256>>>(input, target, neg, out, B, T);
}

// round 13
// speedup vs baseline: 1.5860x; 1.1219x over previous
#include <cuda_runtime.h>
#include <math.h>
#include <limits.h>

// WARP loss, R13: R12 (warp-per-row, double-buffered chunk scan, lazy-16
// gather) with two fixes from the R12 profile:
//  - 64-thread blocks: grid 2048 -> 13.8 blocks/SM (max/mean = 1.01) vs
//    512 blocks -> 3.46/SM (68 SMs carried +16% work). Kills SM stragglers.
//  - CV=5: 2.5KB chunks, 16/row -> deep-row tail 8 rounds (was 10) for
//    +0.5KB/row expected over-read.
// Traffic ledger unchanged: ~101MB.

#define FULL 0xFFFFFFFFu
#define BATCH1 16
#define CV 5                       // float4 per lane per chunk (2.5KB/chunk)
#define CHUNK (CV * 32)            // 160 float4 per chunk

__global__ __launch_bounds__(64, 16)
void warp_loss_kernel(const float* __restrict__ input,
                      const float* __restrict__ target,
                      const int*   __restrict__ neg,
                      float* __restrict__ out,
                      int B, int T) {
    constexpr int Y    = 10000;
    constexpr int nvec = Y >> 2;                       // 2500 float4
    constexpr int NCH  = (nvec + CHUNK - 1) / CHUNK;   // 16 chunks

    const int gw   = blockIdx.x * 2 + (threadIdx.x >> 5);
    const int lane = threadIdx.x & 31;
    if (gw >= B) return;                               // warp-uniform

    const float* irow = input  + (size_t)gw * Y;
    const float* trow = target + (size_t)gw * Y;
    const float4* tv  = reinterpret_cast<const float4*>(trow);
    const float4 zero4 = make_float4(0.f, 0.f, 0.f, 0.f);

    // --- eager gather of first BATCH1 trials (independent of sp) ---
    int c_pre = 0;
    if (lane < BATCH1) c_pre = __ldg(&neg[(size_t)gw * T + lane]);
    const float sc_pre = __ldg(&irow[c_pre]);          // lanes>=16: bcast irow[0]

#define LOADC(buf, ch)                                              \
    {                                                               \
        _Pragma("unroll")                                           \
        for (int k = 0; k < CV; k++) {                              \
            const int _i = (ch) * CHUNK + k * 32 + lane;            \
            buf[k] = (_i < nvec) ? __ldg(&tv[_i]) : zero4;          \
        }                                                           \
    }
#define TESTC(buf, ch, pvar)                                        \
    {                                                               \
        _Pragma("unroll")                                           \
        for (int k = 0; k < CV; k++) {                              \
            const int _i = (ch) * CHUNK + k * 32 + lane;            \
            if (buf[k].x != 0.0f) pvar = 4 * _i;                    \
            if (buf[k].y != 0.0f) pvar = 4 * _i + 1;                \
            if (buf[k].z != 0.0f) pvar = 4 * _i + 2;                \
            if (buf[k].w != 0.0f) pvar = 4 * _i + 3;                \
        }                                                           \
    }

    // --- double-buffered scan: prefetch ch+1 while testing ch ---
    int pos = -1;
    {
        float4 A[CV], Bb[CV];
        LOADC(A, 0);
#pragma unroll
        for (int ch = 0; ch < NCH; ch += 2) {
            if (ch + 1 < NCH) LOADC(Bb, ch + 1);
            int p = -1;
            TESTC(A, ch, p);
            if (__ballot_sync(FULL, p >= 0)) {
                pos = __reduce_min_sync(FULL, p >= 0 ? p : INT_MAX);
                break;
            }
            if (ch + 2 < NCH) LOADC(A, ch + 2);
            p = -1;
            if (ch + 1 < NCH) TESTC(Bb, ch + 1, p);
            if (__ballot_sync(FULL, p >= 0)) {
                pos = __reduce_min_sync(FULL, p >= 0 ? p : INT_MAX);
                break;
            }
        }
    }
    if (pos < 0) pos = 0;                              // defensive (one-hot row)

    const float sp = __ldg(&irow[pos]);                // broadcast load

    // --- first accepted among trials 0..15 (scores already in regs) ---
    const bool acc = (lane < BATCH1) && (1.0f + sc_pre - sp >= 0.0f);
    const unsigned m = __ballot_sync(FULL, acc);
    if (m) {
        const int first = __ffs(m) - 1;
        const float sn = __shfl_sync(FULL, sc_pre, first);
        if (lane == 0) {
            const int num_trials = first + 1;
            const float L = logf((float)((Y - 1) / num_trials));
            atomicAdd(out, L * (1.0f - sp + sn));
        }
    } else {
        // --- fallback (rare, ~0.3%): trials BATCH1..T-1, 32 at a time ---
        for (int t0 = BATCH1; t0 < T; t0 += 32) {
            const int t = t0 + lane;
            int c = 0;
            if (t < T) c = __ldg(&neg[(size_t)gw * T + t]);
            const float sc = __ldg(&irow[c]);
            const bool a2 = (t < T) && (1.0f + sc - sp >= 0.0f);
            const unsigned m2 = __ballot_sync(FULL, a2);
            if (m2) {
                const int fl = __ffs(m2) - 1;
                const float sn = __shfl_sync(FULL, sc, fl);
                if (lane == 0) {
                    const int num_trials = t0 + fl + 1;
                    const float L = logf((float)((Y - 1) / num_trials));
                    atomicAdd(out, L * (1.0f - sp + sn));
                }
                break;
            }
        }
    }
#undef LOADC
#undef TESTC
}

extern "C" void kernel_launch(void* const* d_in, const int* in_sizes, int n_in,
                              void* d_out, int out_size) {
    const float* input  = (const float*)d_in[0];
    const float* target = (const float*)d_in[1];
    const int*   neg    = (const int*)d_in[2];
    float* out = (float*)d_out;

    const int Y = 10000;                 // fixed by problem spec
    const int B = in_sizes[0] / Y;       // 4096
    const int T = in_sizes[2] / B;       // 128

    cudaMemsetAsync(out, 0, (size_t)out_size * sizeof(float), 0);
    warp_loss_kernel<<<(B + 1) / 2, 64>>>(input, target, neg, out, B, T);
}